// round 10
// baseline (speedup 1.0000x reference)
#include <cuda_runtime.h>
#include <cuda_bf16.h>
#include <math.h>
#include <stdint.h>

#define N_NODES 50000
#define EDGES   800000
#define ET      (EDGES + N_NODES)   // edges + self loops = 850000
#define NHEAD   8
#define DH      32
#define FDIM    256

// ---------------- scratch (device globals; no allocation allowed) ------------
__device__ float g_h0[N_NODES * FDIM];
__device__ float g_hbuf[3 * N_NODES * FDIM];   // per-metapath intermediate h
__device__ float g_hp[3 * N_NODES * FDIM];     // per-metapath projected feats
__device__ float g_embs[3 * N_NODES * FDIM];
__device__ float g_ssrc[3 * N_NODES * NHEAD];
__device__ float g_sdst[3 * N_NODES * NHEAD];
__device__ float g_hsem[3 * N_NODES * 128];
__device__ float g_z[N_NODES * FDIM];
__device__ float g_hcls[N_NODES * 128];

// CSR (built once per launch; edges constant)
#define SCAN_CHUNK  4096
#define SCAN_BLOCKS 13   // ceil(50000/4096)
__device__ int g_deg[3 * N_NODES];
__device__ int g_fill[3 * N_NODES];
__device__ int g_ptr[3 * (N_NODES + 1)];
__device__ int g_csr[3 * ET];
__device__ int g_blksum[3 * SCAN_BLOCKS];
__device__ int g_blkoff[3 * SCAN_BLOCKS];

// ================= CSR build =================================================
__global__ void csr_zero_kernel() {
    int idx = blockIdx.x * blockDim.x + threadIdx.x;
    if (idx < 3 * N_NODES) g_deg[idx] = 0;
}

__global__ void csr_hist_kernel(const int* __restrict__ edges) {
    int idx = blockIdx.x * blockDim.x + threadIdx.x;
    int p = blockIdx.y;
    if (idx >= ET) return;
    int d = (idx < EDGES) ? edges[(size_t)p * 2 * EDGES + EDGES + idx] : idx - EDGES;
    atomicAdd(&g_deg[p * N_NODES + d], 1);
}

// phase 1: per-block (4096-elem chunk) exclusive scan + block totals
__global__ void __launch_bounds__(1024) csr_scan1_kernel() {
    int p = blockIdx.y, b = blockIdx.x;
    int tid = threadIdx.x, lane = tid & 31, wid = tid >> 5;
    __shared__ int swarp[32];
    int base = b * SCAN_CHUNK + tid * 4;
    int v[4];
#pragma unroll
    for (int j = 0; j < 4; j++) {
        int i = base + j;
        v[j] = (i < N_NODES) ? g_deg[p * N_NODES + i] : 0;
    }
    int tsum = v[0] + v[1] + v[2] + v[3];
    int incl = tsum;
#pragma unroll
    for (int off = 1; off < 32; off <<= 1) {
        int t = __shfl_up_sync(0xffffffffu, incl, off);
        if (lane >= off) incl += t;
    }
    if (lane == 31) swarp[wid] = incl;
    __syncthreads();
    if (wid == 0) {
        int s = swarp[lane];
#pragma unroll
        for (int off = 1; off < 32; off <<= 1) {
            int t = __shfl_up_sync(0xffffffffu, s, off);
            if (lane >= off) s += t;
        }
        swarp[lane] = s;
    }
    __syncthreads();
    int ex = incl - tsum + (wid ? swarp[wid - 1] : 0);
    int run = ex;
#pragma unroll
    for (int j = 0; j < 4; j++) {
        int i = base + j;
        if (i < N_NODES) g_ptr[p * (N_NODES + 1) + i] = run;
        run += v[j];
    }
    if (tid == 1023) g_blksum[p * SCAN_BLOCKS + b] = run;
}

// phase 2: scan the 13 block sums per metapath (tiny)
__global__ void csr_scan2_kernel() {
    int p = threadIdx.x;
    if (p >= 3) return;
    int run = 0;
    for (int b = 0; b < SCAN_BLOCKS; b++) {
        g_blkoff[p * SCAN_BLOCKS + b] = run;
        run += g_blksum[p * SCAN_BLOCKS + b];
    }
    g_ptr[p * (N_NODES + 1) + N_NODES] = run;
}

// phase 3: add block offsets, mirror into g_fill
__global__ void csr_scan3_kernel() {
    int idx = blockIdx.x * blockDim.x + threadIdx.x;
    if (idx >= 3 * N_NODES) return;
    int p = idx / N_NODES, i = idx - p * N_NODES;
    int v = g_ptr[p * (N_NODES + 1) + i] + g_blkoff[p * SCAN_BLOCKS + i / SCAN_CHUNK];
    g_ptr[p * (N_NODES + 1) + i] = v;
    g_fill[p * N_NODES + i] = v;
}

__global__ void csr_scatter_kernel(const int* __restrict__ edges) {
    int idx = blockIdx.x * blockDim.x + threadIdx.x;
    int p = blockIdx.y;
    if (idx >= ET) return;
    int s, d;
    if (idx < EDGES) {
        s = edges[(size_t)p * 2 * EDGES + idx];
        d = edges[(size_t)p * 2 * EDGES + EDGES + idx];
    } else {
        s = idx - EDGES; d = s;
    }
    int pos = atomicAdd(&g_fill[p * N_NODES + d], 1);
    g_csr[(size_t)p * ET + pos] = s;
}

// ================= tf32 tensor-core GEMM (double-buffered smem) ==============
#define AS_WORDS    (128 * 36)
#define BS_WORDS    (32 * 132)
#define STAGE_WORDS (AS_WORDS + BS_WORDS)
#define GEMM_SMEM_BYTES (2 * STAGE_WORDS * 4)

__device__ __forceinline__ uint32_t f2tf32(float f) {
    uint32_t r;
    asm("cvt.rna.tf32.f32 %0, %1;" : "=r"(r) : "f"(f));
    return r;
}

__device__ __forceinline__ void mma_tf32(float* cc,
                                         uint32_t a0, uint32_t a1, uint32_t a2, uint32_t a3,
                                         uint32_t b0, uint32_t b1) {
    asm volatile(
        "mma.sync.aligned.m16n8k8.row.col.f32.tf32.tf32.f32 "
        "{%0,%1,%2,%3}, {%4,%5,%6,%7}, {%8,%9}, {%0,%1,%2,%3};"
        : "+f"(cc[0]), "+f"(cc[1]), "+f"(cc[2]), "+f"(cc[3])
        : "r"(a0), "r"(a1), "r"(a2), "r"(a3), "r"(b0), "r"(b1));
}

template <int EPI>  // 0 none, 1 +bias, 2 +bias+relu
__global__ void __launch_bounds__(256)
gemm_tf32(const float* __restrict__ A, const float* __restrict__ B,
          const float* __restrict__ bias, float* __restrict__ C,
          int M, int K, int Nc) {
    extern __shared__ uint32_t sm[];

    const int bm = blockIdx.x * 128;
    const int bn = blockIdx.y * 128;
    const int tid = threadIdx.x;
    const int lane = tid & 31;
    const int warp = tid >> 5;
    const int wm = (warp & 1) * 64;
    const int wn = (warp >> 1) * 32;
    const int gq = lane >> 2;
    const int cq = lane & 3;

    const int ar = tid >> 3;
    const int ac = (tid & 7) * 4;
    const int br = tid >> 5;
    const int bc = (tid & 31) * 4;

    const bool avalid0 = (bm + ar) < M;
    const bool avalid1 = (bm + ar + 32) < M;
    const bool avalid2 = (bm + ar + 64) < M;
    const bool avalid3 = (bm + ar + 96) < M;

    float4 ra[4], rb[4];

#define LOAD_REGS(k0)                                                            \
    {                                                                            \
        ra[0] = avalid0 ? *(const float4*)(A + (size_t)(bm + ar) * K + (k0) + ac)        : make_float4(0.f,0.f,0.f,0.f); \
        ra[1] = avalid1 ? *(const float4*)(A + (size_t)(bm + ar + 32) * K + (k0) + ac)   : make_float4(0.f,0.f,0.f,0.f); \
        ra[2] = avalid2 ? *(const float4*)(A + (size_t)(bm + ar + 64) * K + (k0) + ac)   : make_float4(0.f,0.f,0.f,0.f); \
        ra[3] = avalid3 ? *(const float4*)(A + (size_t)(bm + ar + 96) * K + (k0) + ac)   : make_float4(0.f,0.f,0.f,0.f); \
        rb[0] = *(const float4*)(B + (size_t)((k0) + br)      * Nc + bn + bc);   \
        rb[1] = *(const float4*)(B + (size_t)((k0) + br + 8)  * Nc + bn + bc);   \
        rb[2] = *(const float4*)(B + (size_t)((k0) + br + 16) * Nc + bn + bc);   \
        rb[3] = *(const float4*)(B + (size_t)((k0) + br + 24) * Nc + bn + bc);   \
    }

#define STORE_STAGE(buf)                                                         \
    {                                                                            \
        uint32_t* as_ = sm + (buf) * STAGE_WORDS;                                \
        uint32_t* bs_ = sm + (buf) * STAGE_WORDS + AS_WORDS;                     \
        _Pragma("unroll")                                                        \
        for (int i = 0; i < 4; i++) {                                            \
            int row = ar + 32 * i;                                               \
            as_[row * 36 + ac + 0] = f2tf32(ra[i].x);                            \
            as_[row * 36 + ac + 1] = f2tf32(ra[i].y);                            \
            as_[row * 36 + ac + 2] = f2tf32(ra[i].z);                            \
            as_[row * 36 + ac + 3] = f2tf32(ra[i].w);                            \
            int kr = br + 8 * i;                                                 \
            bs_[kr * 132 + bc + 0] = f2tf32(rb[i].x);                            \
            bs_[kr * 132 + bc + 1] = f2tf32(rb[i].y);                            \
            bs_[kr * 132 + bc + 2] = f2tf32(rb[i].z);                            \
            bs_[kr * 132 + bc + 3] = f2tf32(rb[i].w);                            \
        }                                                                        \
    }

#define COMPUTE_TILE(buf)                                                        \
    {                                                                            \
        const uint32_t* as_ = sm + (buf) * STAGE_WORDS;                          \
        const uint32_t* bs_ = sm + (buf) * STAGE_WORDS + AS_WORDS;               \
        _Pragma("unroll")                                                        \
        for (int ks = 0; ks < 4; ks++) {                                         \
            const int kb = ks * 8;                                               \
            uint32_t af[4][4], bf[4][2];                                         \
            _Pragma("unroll")                                                    \
            for (int i = 0; i < 4; i++) {                                        \
                int r0 = wm + i * 16 + gq;                                       \
                af[i][0] = as_[r0 * 36 + kb + cq];                               \
                af[i][1] = as_[(r0 + 8) * 36 + kb + cq];                         \
                af[i][2] = as_[r0 * 36 + kb + cq + 4];                           \
                af[i][3] = as_[(r0 + 8) * 36 + kb + cq + 4];                     \
            }                                                                    \
            _Pragma("unroll")                                                    \
            for (int j = 0; j < 4; j++) {                                        \
                int col = wn + j * 8 + gq;                                       \
                bf[j][0] = bs_[(kb + cq) * 132 + col];                           \
                bf[j][1] = bs_[(kb + cq + 4) * 132 + col];                       \
            }                                                                    \
            _Pragma("unroll")                                                    \
            for (int i = 0; i < 4; i++)                                          \
                _Pragma("unroll")                                                \
                for (int j = 0; j < 4; j++)                                      \
                    mma_tf32(acc[i][j], af[i][0], af[i][1], af[i][2], af[i][3],  \
                             bf[j][0], bf[j][1]);                                \
        }                                                                        \
    }

    LOAD_REGS(0);
    STORE_STAGE(0);
    __syncthreads();

    float acc[4][4][4];
#pragma unroll
    for (int i = 0; i < 4; i++)
#pragma unroll
        for (int j = 0; j < 4; j++)
#pragma unroll
            for (int q = 0; q < 4; q++) acc[i][j][q] = 0.f;

    int cur = 0;
    for (int k0 = 32; k0 < K; k0 += 32) {
        LOAD_REGS(k0);
        COMPUTE_TILE(cur);
        STORE_STAGE(cur ^ 1);
        __syncthreads();
        cur ^= 1;
    }
    COMPUTE_TILE(cur);

#undef LOAD_REGS
#undef STORE_STAGE
#undef COMPUTE_TILE

#pragma unroll
    for (int i = 0; i < 4; i++) {
        int r0 = bm + wm + i * 16 + gq;
        int r1 = r0 + 8;
#pragma unroll
        for (int j = 0; j < 4; j++) {
            int col = bn + wn + j * 8 + 2 * cq;
            float2 v0 = make_float2(acc[i][j][0], acc[i][j][1]);
            float2 v1 = make_float2(acc[i][j][2], acc[i][j][3]);
            if (EPI >= 1) {
                float2 bv = *(const float2*)(bias + col);
                v0.x += bv.x; v0.y += bv.y; v1.x += bv.x; v1.y += bv.y;
            }
            if (EPI == 2) {
                v0.x = fmaxf(v0.x, 0.f); v0.y = fmaxf(v0.y, 0.f);
                v1.x = fmaxf(v1.x, 0.f); v1.y = fmaxf(v1.y, 0.f);
            }
            if (r0 < M) *(float2*)(C + (size_t)r0 * Nc + col) = v0;
            if (r1 < M) *(float2*)(C + (size_t)r1 * Nc + col) = v1;
        }
    }
}

// -------- per-(node,head) attention logits -----------------------------------
__global__ void scores_kernel(const float* __restrict__ hp,
                              const float* __restrict__ asrc,
                              const float* __restrict__ adst,
                              float* __restrict__ ssrc,
                              float* __restrict__ sdst) {
    int idx = blockIdx.x * blockDim.x + threadIdx.x;
    if (idx >= N_NODES * NHEAD) return;
    int n = idx >> 3, h = idx & 7;
    const float4* v = (const float4*)(hp + (size_t)n * FDIM + h * DH);
    const float4* a = (const float4*)(asrc + h * DH);
    const float4* b = (const float4*)(adst + h * DH);
    float s1 = 0.f, s2 = 0.f;
#pragma unroll
    for (int i = 0; i < 8; i++) {
        float4 x = v[i], p = a[i], q = b[i];
        s1 += x.x * p.x + x.y * p.y + x.z * p.z + x.w * p.w;
        s2 += x.x * q.x + x.y * q.y + x.z * q.z + x.w * q.w;
    }
    ssrc[idx] = s1;
    sdst[idx] = s2;
}

// ======== single-pass aggregation ============================================
__global__ void __launch_bounds__(64)
agg_kernel(const int* __restrict__ ptr, const int* __restrict__ csrc,
           const float* __restrict__ hp,
           const float* __restrict__ ssrc, const float* __restrict__ sdst,
           const float* __restrict__ bias, float* __restrict__ out) {
    const int n = blockIdx.x;
    const int t = threadIdx.x;
    const int lane = t & 31;
    const int p0 = ptr[n];
    const int deg = ptr[n + 1] - p0;
    __shared__ int se[64];

    const int myh = t >> 3;
    const float mysd = sdst[(size_t)n * 8 + myh];
    const bool leader = (lane & 7) == 0;

    float4 acc = make_float4(0.f, 0.f, 0.f, 0.f);
    float wsum = 0.f;

    for (int c0 = 0; c0 < deg; c0 += 64) {
        int cnt = min(64, deg - c0);
        __syncthreads();
        if (t < cnt) se[t] = csrc[p0 + c0 + t];
        __syncthreads();
        for (int i = 0; i < cnt; i++) {
            int s = se[i];
            float w = 0.f;
            if (leader) {
                float e = ssrc[(size_t)s * 8 + myh] + mysd;
                e = e > 0.f ? e : 0.2f * e;
                w = expf(e);
                wsum += w;
            }
            w = __shfl_sync(0xffffffffu, w, lane & 24);
            float4 x = ((const float4*)(hp + (size_t)s * FDIM))[t];
            acc.x = fmaf(w, x.x, acc.x);
            acc.y = fmaf(w, x.y, acc.y);
            acc.z = fmaf(w, x.z, acc.z);
            acc.w = fmaf(w, x.w, acc.w);
        }
    }

    float wtot = __shfl_sync(0xffffffffu, wsum, lane & 24);
    float inv = 1.f / wtot;

    float4 bv = ((const float4*)bias)[t];
    float v;
    v = fmaf(acc.x, inv, bv.x); acc.x = v > 0.f ? v : expm1f(v);
    v = fmaf(acc.y, inv, bv.y); acc.y = v > 0.f ? v : expm1f(v);
    v = fmaf(acc.z, inv, bv.z); acc.z = v > 0.f ? v : expm1f(v);
    v = fmaf(acc.w, inv, bv.w); acc.w = v > 0.f ? v : expm1f(v);
    ((float4*)(out + (size_t)n * FDIM))[t] = acc;
}

// -------- semantic attention fuse: scores -> softmax -> weighted sum ---------
__global__ void __launch_bounds__(128)
semfuse_kernel(const float* __restrict__ semW2) {
    int n = blockIdx.x;
    int t = threadIdx.x;  // 128
    __shared__ float red[4];
    __shared__ float w[3];
    float sloc[3];
    for (int p = 0; p < 3; p++) {
        float v = tanhf(g_hsem[((size_t)p * N_NODES + n) * 128 + t]) * semW2[t];
#pragma unroll
        for (int o = 16; o; o >>= 1) v += __shfl_down_sync(0xffffffffu, v, o);
        if ((t & 31) == 0) red[t >> 5] = v;
        __syncthreads();
        if (t == 0) sloc[p] = red[0] + red[1] + red[2] + red[3];
        __syncthreads();
    }
    if (t == 0) {
        float mx = fmaxf(sloc[0], fmaxf(sloc[1], sloc[2]));
        float e0 = expf(sloc[0] - mx), e1 = expf(sloc[1] - mx), e2 = expf(sloc[2] - mx);
        float inv = 1.f / (e0 + e1 + e2);
        w[0] = e0 * inv; w[1] = e1 * inv; w[2] = e2 * inv;
    }
    __syncthreads();
    for (int c = t; c < FDIM; c += 128) {
        float acc = 0.f;
#pragma unroll
        for (int p = 0; p < 3; p++)
            acc += w[p] * g_embs[((size_t)p * N_NODES + n) * FDIM + c];
        g_z[(size_t)n * FDIM + c] = acc;
    }
}

// -------- final 128->2 head --------------------------------------------------
__global__ void __launch_bounds__(128)
cls_final_kernel(const float* __restrict__ W2, const float* __restrict__ b2,
                 float* __restrict__ out) {
    int n = blockIdx.x;
    int t = threadIdx.x;  // 128
    float h = g_hcls[(size_t)n * 128 + t];
    float a0 = h * W2[t * 2 + 0];
    float a1 = h * W2[t * 2 + 1];
    __shared__ float r0[4], r1[4];
#pragma unroll
    for (int o = 16; o; o >>= 1) {
        a0 += __shfl_down_sync(0xffffffffu, a0, o);
        a1 += __shfl_down_sync(0xffffffffu, a1, o);
    }
    if ((t & 31) == 0) { r0[t >> 5] = a0; r1[t >> 5] = a1; }
    __syncthreads();
    if (t == 0) {
        out[n * 2 + 0] = r0[0] + r0[1] + r0[2] + r0[3] + b2[0];
        out[n * 2 + 1] = r1[0] + r1[1] + r1[2] + r1[3] + b2[1];
    }
}

// ---------------- host -------------------------------------------------------
extern "C" void kernel_launch(void* const* d_in, const int* in_sizes, int n_in,
                              void* d_out, int out_size) {
    const float* x       = (const float*)d_in[0];
    const int*   edges   = (const int*)d_in[1];
    const float* proj_W  = (const float*)d_in[2];
    const float* proj_b  = (const float*)d_in[3];
    const float* gat_W   = (const float*)d_in[4];
    const float* gat_asrc= (const float*)d_in[5];
    const float* gat_adst= (const float*)d_in[6];
    const float* gat_b   = (const float*)d_in[7];
    const float* sem_W1  = (const float*)d_in[8];
    const float* sem_b1  = (const float*)d_in[9];
    const float* sem_W2  = (const float*)d_in[10];
    const float* cls_W1  = (const float*)d_in[11];
    const float* cls_b1  = (const float*)d_in[12];
    const float* cls_W2  = (const float*)d_in[13];
    const float* cls_b2  = (const float*)d_in[14];
    float* out = (float*)d_out;

    float *p_h0, *p_hbuf, *p_hp, *p_embs, *p_hsem, *p_z, *p_hcls, *p_ssrc, *p_sdst;
    int *p_ptr, *p_csr;
    cudaGetSymbolAddress((void**)&p_h0,   g_h0);
    cudaGetSymbolAddress((void**)&p_hbuf, g_hbuf);
    cudaGetSymbolAddress((void**)&p_hp,   g_hp);
    cudaGetSymbolAddress((void**)&p_embs, g_embs);
    cudaGetSymbolAddress((void**)&p_hsem, g_hsem);
    cudaGetSymbolAddress((void**)&p_z,    g_z);
    cudaGetSymbolAddress((void**)&p_hcls, g_hcls);
    cudaGetSymbolAddress((void**)&p_ssrc, g_ssrc);
    cudaGetSymbolAddress((void**)&p_sdst, g_sdst);
    cudaGetSymbolAddress((void**)&p_ptr,  g_ptr);
    cudaGetSymbolAddress((void**)&p_csr,  g_csr);

    // streams/events/attributes set ONCE, outside graph capture
    static cudaStream_t st1 = nullptr, st2 = nullptr;
    static cudaEvent_t ev0, ev1, ev2, ev3, ev4;
    if (st1 == nullptr) {
        cudaStreamCreateWithFlags(&st1, cudaStreamNonBlocking);
        cudaStreamCreateWithFlags(&st2, cudaStreamNonBlocking);
        cudaEventCreateWithFlags(&ev0, cudaEventDisableTiming);
        cudaEventCreateWithFlags(&ev1, cudaEventDisableTiming);
        cudaEventCreateWithFlags(&ev2, cudaEventDisableTiming);
        cudaEventCreateWithFlags(&ev3, cudaEventDisableTiming);
        cudaEventCreateWithFlags(&ev4, cudaEventDisableTiming);
        cudaFuncSetAttribute(gemm_tf32<0>, cudaFuncAttributeMaxDynamicSharedMemorySize, GEMM_SMEM_BYTES);
        cudaFuncSetAttribute(gemm_tf32<1>, cudaFuncAttributeMaxDynamicSharedMemorySize, GEMM_SMEM_BYTES);
        cudaFuncSetAttribute(gemm_tf32<2>, cudaFuncAttributeMaxDynamicSharedMemorySize, GEMM_SMEM_BYTES);
    }

    const int M = N_NODES;
    dim3 gproj((M + 127) / 128, 2);
    const int scoreGrid = (N_NODES * NHEAD + 255) / 256;

    // ---- fork: proj GEMM on st1, CSR build on main ----
    cudaEventRecord(ev0, 0);
    cudaStreamWaitEvent(st1, ev0, 0);
    gemm_tf32<1><<<gproj, 256, GEMM_SMEM_BYTES, st1>>>(x, proj_W, proj_b, p_h0, M, 128, 256);
    cudaEventRecord(ev1, st1);

    csr_zero_kernel<<<(3 * N_NODES + 255) / 256, 256>>>();
    dim3 ge((ET + 255) / 256, 3);
    csr_hist_kernel<<<ge, 256>>>(edges);
    csr_scan1_kernel<<<dim3(SCAN_BLOCKS, 3), 1024>>>();
    csr_scan2_kernel<<<1, 3>>>();
    csr_scan3_kernel<<<(3 * N_NODES + 255) / 256, 256>>>();
    csr_scatter_kernel<<<ge, 256>>>(edges);

    cudaStreamWaitEvent(0, ev1, 0);
    cudaEventRecord(ev2, 0);                 // CSR + h0 both ready
    cudaStreamWaitEvent(st1, ev2, 0);
    cudaStreamWaitEvent(st2, ev2, 0);

    // ---- 3 independent meta-path chains, one per stream ----
    cudaStream_t chains[3] = { (cudaStream_t)0, st1, st2 };
    dim3 gsem((M + 127) / 128, 1);
    for (int p = 0; p < 3; p++) {
        cudaStream_t s = chains[p];
        const int* ptr = p_ptr + (size_t)p * (N_NODES + 1);
        const int* csr = p_csr + (size_t)p * ET;
        float* hp_p  = p_hp   + (size_t)p * N_NODES * FDIM;
        float* h_p   = p_hbuf + (size_t)p * N_NODES * FDIM;
        float* ss_p  = p_ssrc + (size_t)p * N_NODES * NHEAD;
        float* sd_p  = p_sdst + (size_t)p * N_NODES * NHEAD;
        float* emb_p = p_embs + (size_t)p * N_NODES * FDIM;
        for (int l = 0; l < 2; l++) {
            const float* W  = gat_W    + (size_t)(p * 2 + l) * 256 * 256;
            const float* as = gat_asrc + (size_t)(p * 2 + l) * NHEAD * DH;
            const float* ad = gat_adst + (size_t)(p * 2 + l) * NHEAD * DH;
            const float* gb = gat_b    + (size_t)(p * 2 + l) * 256;
            const float* hin = (l == 0) ? p_h0 : h_p;
            float* hout = (l == 0) ? h_p : emb_p;

            gemm_tf32<0><<<gproj, 256, GEMM_SMEM_BYTES, s>>>(hin, W, nullptr, hp_p, M, 256, 256);
            scores_kernel<<<scoreGrid, 256, 0, s>>>(hp_p, as, ad, ss_p, sd_p);
            agg_kernel<<<N_NODES, 64, 0, s>>>(ptr, csr, hp_p, ss_p, sd_p, gb, hout);
        }
        // per-chain slice of the semantic-attention GEMM (overlaps other chains)
        gemm_tf32<1><<<gsem, 256, GEMM_SMEM_BYTES, s>>>(
            emb_p, sem_W1, sem_b1, p_hsem + (size_t)p * N_NODES * 128, M, 256, 128);
    }

    // ---- join ----
    cudaEventRecord(ev3, st1);
    cudaEventRecord(ev4, st2);
    cudaStreamWaitEvent(0, ev3, 0);
    cudaStreamWaitEvent(0, ev4, 0);

    // semantic softmax + weighted sum
    semfuse_kernel<<<N_NODES, 128>>>(sem_W2);

    // classifier
    dim3 gcls((M + 127) / 128, 1);
    gemm_tf32<2><<<gcls, 256, GEMM_SMEM_BYTES>>>(p_z, cls_W1, cls_b1, p_hcls, M, 256, 128);
    cls_final_kernel<<<N_NODES, 128>>>(cls_W2, cls_b2, out);
}